// round 1
// baseline (speedup 1.0000x reference)
#include <cuda_runtime.h>
#include <math.h>

// YOLO layer: input x (BS=64, NA*(5+NC)=255, G=44, G=44) f32
// output (BS, NA*G*G=5808, 85) f32
//   out[b, a*G*G + gy*G + gx, c] = f(x[b, a*85 + c, gy, gx])
//   c==0: (sigmoid(v)+gx)*8        c==1: (sigmoid(v)+gy)*8
//   c==2: exp(v)*anchor_w[a]       c==3: exp(v)*anchor_h[a]
//   c>=4: sigmoid(v)
// Pure memory-bound transposed elementwise map -> 32x32 smem tiled transpose.

#define G44   44
#define GG    1936      // 44*44
#define CH    85        // 5 + 80
#define NA    3
#define TILE  32
#define BROWS 8         // blockDim.y

// raw anchors (scaled_anchor * STRIDE == raw anchor, STRIDE=8 cancels)
__constant__ float c_aw[NA] = {10.0f, 16.0f, 33.0f};
__constant__ float c_ah[NA] = {13.0f, 30.0f, 23.0f};

__device__ __forceinline__ float sigmoidf_(float v) {
    return 1.0f / (1.0f + __expf(-v));
}

__global__ __launch_bounds__(TILE * BROWS)
void yolo_transpose_kernel(const float* __restrict__ x, float* __restrict__ out) {
    __shared__ float tile[TILE][TILE + 1];   // +1 pad: conflict-free transposed read

    const int ba  = blockIdx.z;              // 0..191 = b*NA + a
    const int a   = ba % NA;
    const int ch0 = blockIdx.y * TILE;       // 0, 32, 64
    const int s0  = blockIdx.x * TILE;       // spatial tile base

    const float* __restrict__ ibase = x   + (size_t)ba * CH * GG;
    float*       __restrict__ obase = out + (size_t)ba * (size_t)GG * CH;

    const float aw = c_aw[a];
    const float ah = c_ah[a];

    // ---- read phase: coalesced along spatial dim, transform in-flight ----
    {
        const int s = s0 + threadIdx.x;
        if (s < GG) {
            const int gx = s % G44;
            const int gy = s / G44;
            #pragma unroll
            for (int r = threadIdx.y; r < TILE; r += BROWS) {
                const int ch = ch0 + r;
                if (ch < CH) {
                    const float v = __ldg(&ibase[(size_t)ch * GG + s]);
                    float t;
                    if (ch == 0)      t = (sigmoidf_(v) + (float)gx) * 8.0f;
                    else if (ch == 1) t = (sigmoidf_(v) + (float)gy) * 8.0f;
                    else if (ch == 2) t = __expf(v) * aw;
                    else if (ch == 3) t = __expf(v) * ah;
                    else              t = sigmoidf_(v);
                    tile[r][threadIdx.x] = t;
                }
            }
        }
    }

    __syncthreads();

    // ---- write phase: coalesced along channel dim ----
    {
        const int ch = ch0 + threadIdx.x;
        if (ch < CH) {
            #pragma unroll
            for (int r = threadIdx.y; r < TILE; r += BROWS) {
                const int s = s0 + r;
                if (s < GG)
                    obase[(size_t)s * CH + ch] = tile[threadIdx.x][r];
            }
        }
    }
}

extern "C" void kernel_launch(void* const* d_in, const int* in_sizes, int n_in,
                              void* d_out, int out_size) {
    const float* x = (const float*)d_in[0];
    float* out = (float*)d_out;

    dim3 block(TILE, BROWS);
    dim3 grid((GG + TILE - 1) / TILE,   // 61 spatial tiles
              (CH + TILE - 1) / TILE,   // 3 channel tiles
              64 * NA);                 // 192 (b,a) matrices
    yolo_transpose_kernel<<<grid, block>>>(x, out);
}